// round 11
// baseline (speedup 1.0000x reference)
#include <cuda_runtime.h>
#include <math.h>
#include <cstddef>

// B=256, T=64, D=16, S=64, H=128, O=8
#define NTHR 256
#define PREPT 256

// Pair-packed Wf3: g_Wf3P[(q*1024 + n)*2 + r] = Wf3[n*128 + 2*q + r]  (512 KB)
__device__ __align__(16) float g_Wf3P[64 * 1024 * 2];

__constant__ float cC[6]  = {0.0f, 0.161f, 0.327f, 0.9f, 0.9800255409045097f, 1.0f};
__constant__ float cBw[6] = {0.09646076681806523f, 0.01f, 0.4798896504144996f,
                             1.379008574103742f, -3.290069515436081f, 2.324710524099774f};
__constant__ float cA[6][5] = {
    {0.f, 0.f, 0.f, 0.f, 0.f},
    {0.161f, 0.f, 0.f, 0.f, 0.f},
    {-0.008480655492356989f, 0.335480655492357f, 0.f, 0.f, 0.f},
    {2.8971530571054935f, -6.359448489975075f, 4.3622954328695815f, 0.f, 0.f},
    {5.325864828439257f, -11.748883564062828f, 7.4955393428898365f, -0.09249506636175525f, 0.f},
    {5.86145544294642f, -12.92096931784711f, 8.159367898576159f, -0.071584973281401f,
     -0.028269050394068383f}};

struct __align__(16) Smem {
    float wc[64 * 256 * 2];    // FULL Wf3 n-quarter, pair-packed [q][n][2]  131072 B
    float Wf2P[64 * 128 * 2];  // [q][i][2]                                   65536 B
    float h2[8][128];          // plain, all 8 rows (3-peer exchange)          4096 B
    float h1[2][128];          // 2 local rows                                 1024 B
    float yj[2][64];           // 2 local rows                                  512 B
    float y[8][64];            //                                              2048 B
    float ks[6][64][8];        // [stage][s][row]                             12288 B
    float dx[8][16];
    float cbv[8][16];
    float ccv[8][16];
    float cdv[8][16];
    float bf1v[128];
    float bf2v[128];
    float bf3loc[256];
    unsigned long long h2_mbar;
    unsigned long long ks_mbar;
};  // 220688 B

// ---------- helpers ----------
__device__ __forceinline__ unsigned long long fma2(unsigned long long a,
                                                   unsigned long long b,
                                                   unsigned long long c) {
    unsigned long long d;
    asm("fma.rn.f32x2 %0, %1, %2, %3;" : "=l"(d) : "l"(a), "l"(b), "l"(c));
    return d;
}
__device__ __forceinline__ float2 u2f(unsigned long long v) {
    float2 r;
    asm("mov.b64 {%0, %1}, %2;" : "=f"(r.x), "=f"(r.y) : "l"(v));
    return r;
}
__device__ __forceinline__ unsigned long long pack2(float x, float y) {
    unsigned long long r;
    asm("mov.b64 %0, {%1, %2};" : "=l"(r) : "f"(x), "f"(y));
    return r;
}
__device__ __forceinline__ unsigned long long ldg64(const float* p) {
    unsigned long long v;
    asm("ld.global.nc.u64 %0, [%1];" : "=l"(v) : "l"(p));
    return v;
}
__device__ __forceinline__ unsigned smem_u32(const void* p) {
    unsigned r;
    asm("{ .reg .u64 t; cvta.to.shared.u64 t, %1; cvt.u32.u64 %0, t; }"
        : "=r"(r) : "l"(p));
    return r;
}
__device__ __forceinline__ unsigned long long lds64(unsigned a) {
    unsigned long long v;
    asm("ld.shared.u64 %0, [%1];" : "=l"(v) : "r"(a));
    return v;
}
// volatile: activation reads must stay after barriers / mbar waits
__device__ __forceinline__ void lds_v2u64(unsigned a, unsigned long long& x,
                                          unsigned long long& y) {
    asm volatile("ld.shared.v2.u64 {%0, %1}, [%2];" : "=l"(x), "=l"(y) : "r"(a));
}
__device__ __forceinline__ unsigned mapa_u32(unsigned laddr, unsigned peer) {
    unsigned r;
    asm("mapa.shared::cluster.u32 %0, %1, %2;" : "=r"(r) : "r"(laddr), "r"(peer));
    return r;
}
__device__ __forceinline__ void mbar_init(unsigned a, unsigned cnt) {
    asm volatile("mbarrier.init.shared.b64 [%0], %1;" :: "r"(a), "r"(cnt) : "memory");
}
__device__ __forceinline__ void mbar_expect_tx(unsigned a, unsigned bytes) {
    asm volatile("mbarrier.arrive.expect_tx.shared.b64 _, [%0], %1;"
                 :: "r"(a), "r"(bytes) : "memory");
}
__device__ __forceinline__ void mbar_wait(unsigned a, unsigned parity) {
    asm volatile(
        "{\n\t.reg .pred P;\n"
        "LW_%=:\n\t"
        "mbarrier.try_wait.parity.acquire.cta.shared::cta.b64 P, [%0], %1, 0x989680;\n\t"
        "@P bra LD_%=;\n\t"
        "bra LW_%=;\n"
        "LD_%=:\n\t}"
        :: "r"(a), "r"(parity) : "memory");
}
__device__ __forceinline__ void st_async32(unsigned dst, float v, unsigned mbar) {
    asm volatile("st.async.shared::cluster.mbarrier::complete_tx::bytes.b32 [%0], %1, [%2];"
                 :: "r"(dst), "f"(v), "r"(mbar) : "memory");
}
__device__ __forceinline__ void st_async64(unsigned dst, unsigned long long v, unsigned mbar) {
    asm volatile("st.async.shared::cluster.mbarrier::complete_tx::bytes.b64 [%0], %1, [%2];"
                 :: "r"(dst), "l"(v), "r"(mbar) : "memory");
}
__device__ __forceinline__ float softplus_f(float x) {
    return fmaxf(x, 0.0f) + log1pf(__expf(-fabsf(x)));
}
__device__ __forceinline__ float tanh_fast(float x) {
    float e = __expf(2.0f * x);
    return 1.0f - 2.0f / (e + 1.0f);
}

__global__ void __launch_bounds__(PREPT, 1) prep_kernel(const float* __restrict__ Wf3) {
    int idx = blockIdx.x * PREPT + threadIdx.x;   // 512 x 256 = 131072
    int q = idx >> 11;
    int rem = idx & 2047;
    int n = rem >> 1;
    int r = rem & 1;
    g_Wf3P[idx] = Wf3[n * 128 + 2 * q + r];
}

__global__ void __launch_bounds__(NTHR, 1) __cluster_dims__(4, 1, 1) cde_kernel(
    const float* __restrict__ ts,
    const float* __restrict__ coeff_d, const float* __restrict__ coeff_c,
    const float* __restrict__ coeff_b, const float* __restrict__ coeff_a,
    const float* __restrict__ Wi1, const float* __restrict__ bi1,
    const float* __restrict__ Wi2, const float* __restrict__ bi2,
    const float* __restrict__ Wf1, const float* __restrict__ bf1,
    const float* __restrict__ Wf2, const float* __restrict__ bf2,
    const float* __restrict__ bf3,
    const float* __restrict__ Wr, const float* __restrict__ br,
    float* __restrict__ out)
{
    extern __shared__ char smraw[];
    Smem& sm = *reinterpret_cast<Smem*>(smraw);
    const int tid = threadIdx.x;
    unsigned rank;
    asm("mov.u32 %0, %%cluster_ctarank;" : "=r"(rank));
    const int b0g = (blockIdx.x >> 2) * 8;   // 8 batch rows per 4-CTA cluster

    const unsigned sbase = smem_u32(smraw);
    const unsigned off_h2 = (unsigned)offsetof(Smem, h2);
    const unsigned off_ks = (unsigned)offsetof(Smem, ks);
    const unsigned my_h2mbar = sbase + (unsigned)offsetof(Smem, h2_mbar);
    const unsigned my_ksmbar = sbase + (unsigned)offsetof(Smem, ks_mbar);
    unsigned peer_h2mbar[3], peer_ksmbar[3], peer_h2base[3], peer_ksbase[3];
    #pragma unroll
    for (int pe = 0; pe < 3; ++pe) {
        unsigned pr = (rank + 1u + (unsigned)pe) & 3u;
        peer_h2mbar[pe] = mapa_u32(my_h2mbar, pr);
        peer_ksmbar[pe] = mapa_u32(my_ksmbar, pr);
        peer_h2base[pe] = mapa_u32(sbase + off_h2, pr);
        peer_ksbase[pe] = mapa_u32(sbase + off_ks, pr);
    }

    if (tid == 0) { mbar_init(my_h2mbar, 1); mbar_init(my_ksmbar, 1); }

    // ---- one-time init ----
    // Full Wf3 n-quarter: wc[q][n_local][2]
    for (int idx = tid; idx < 64 * 512; idx += NTHR) {
        int q = idx >> 9, rem = idx & 511;
        sm.wc[idx] = g_Wf3P[q * 2048 + rank * 512 + rem];
    }
    // Wf2P[(q*128+i)*2+r] = Wf2[i*128 + 2q + r]
    for (int idx = tid; idx < 64 * 128 * 2; idx += NTHR) {
        int q = idx >> 8, rem = idx & 255, i = rem >> 1, r = rem & 1;
        sm.Wf2P[idx] = Wf2[i * 128 + 2 * q + r];
    }
    if (tid < 128) { sm.bf1v[tid] = bf1[tid]; sm.bf2v[tid] = bf2[tid]; }
    if (tid < 256) sm.bf3loc[tid] = bf3[rank * 256 + tid];
    if (tid < 128) {  // x0 = coeff_a[:,0,:] for 8 rows
        int b = tid >> 4, d = tid & 15;
        sm.dx[b][d] = coeff_a[(b0g + b) * 63 * 16 + d];
    }
    __syncthreads();
    asm volatile("barrier.cluster.arrive.aligned;" ::: "memory");
    asm volatile("barrier.cluster.wait.aligned;" ::: "memory");

    // ---- y0 = softplus(x0 @ Wi1^T + bi1) @ Wi2^T + bi2  (8 rows, h2 as scratch) ----
    for (int idx = tid; idx < 1024; idx += NTHR) {
        int b = idx >> 7, jj = idx & 127;
        float acc = bi1[jj];
        #pragma unroll
        for (int d = 0; d < 16; ++d) acc += sm.dx[b][d] * Wi1[jj * 16 + d];
        sm.h2[b][jj] = softplus_f(acc);
    }
    __syncthreads();
    for (int idx = tid; idx < 512; idx += NTHR) {
        int b = idx >> 6, s = idx & 63;
        float acc = bi2[s];
        #pragma unroll 8
        for (int k = 0; k < 128; ++k) acc += sm.h2[b][k] * Wi2[s * 128 + k];
        sm.y[b][s] = acc;
    }
    __syncthreads();
    if (tid < 16) {  // out[:, 0, :] for this CTA's 2 local rows
        int bl = tid >> 3, o = tid & 7;
        int row = (int)rank * 2 + bl;
        float acc = br[o];
        #pragma unroll 8
        for (int s2 = 0; s2 < 64; ++s2) acc += sm.y[row][s2] * Wr[o * 64 + s2];
        out[((b0g + row) * 64 + 0) * 8 + o] = acc;
    }

    // per-thread constants
    const int bl14 = tid >> 7;          // GEMM1/2: local row 0/1
    const int i14  = tid & 127;         // GEMM1/2: output index
    const int row14 = (int)rank * 2 + bl14;
    const unsigned yj_b  = sbase + (unsigned)offsetof(Smem, yj) + (unsigned)bl14 * 256u;
    const unsigned h1_b  = sbase + (unsigned)offsetof(Smem, h1) + (unsigned)bl14 * 512u;
    const unsigned w2_i  = sbase + (unsigned)offsetof(Smem, Wf2P) + (unsigned)i14 * 8u;
    const unsigned h2b   = sbase + off_h2;                         // + row*512 + q*8
    const unsigned wcb   = sbase + (unsigned)offsetof(Smem, wc) + (unsigned)tid * 8u;
    const int d0  = tid & 15;
    const int s_g = (int)rank * 16 + (tid >> 4);
    const bool writer = ((tid & 15) == 0);

    // GEMM1 weights: permanent registers (constant across time loop).
    // w1r[q] = (Wf1[i14][2q], Wf1[i14][2q+1])
    unsigned long long w1r[32];
    #pragma unroll
    for (int q = 0; q < 32; ++q) w1r[q] = ldg64(Wf1 + i14 * 64 + 2 * q);

    unsigned ph = 0;

    // ---- time loop: 63 steps x 6 RK stages ----
    for (int t = 0; t < 63; ++t) {
        float h = ts[t + 1] - ts[t];
        if (tid < 128) {
            int b = tid >> 4, d = tid & 15;
            int base = ((b0g + b) * 63 + t) * 16 + d;
            sm.cbv[b][d] = coeff_b[base];
            sm.ccv[b][d] = coeff_c[base];
            sm.cdv[b][d] = coeff_d[base];
        }

        #pragma unroll 1
        for (int j = 0; j < 6; ++j) {
            if (tid == 0) {
                mbar_expect_tx(my_h2mbar, 3072u);   // 3 peers x 2 rows x 128 x 4B
                mbar_expect_tx(my_ksmbar, 1536u);   // 3 peers x 16 s x 8 rows x 4B
            }
            if (tid < 128) {  // dxdt, all 8 rows
                int b = tid >> 4, d = tid & 15;
                float fr = cC[j] * h;
                sm.dx[b][d] = sm.cbv[b][d] + fr * (2.0f * sm.ccv[b][d] + 3.0f * fr * sm.cdv[b][d]);
            }
            if (tid < 128) {  // yj for 2 local rows
                int bl = tid >> 6, s = tid & 63;
                int row = (int)rank * 2 + bl;
                float v = sm.y[row][s];
                #pragma unroll
                for (int m = 0; m < 5; ++m)
                    if (m < j) v += h * cA[j][m] * sm.ks[m][s][row];
                sm.yj[bl][s] = v;
            }
            __syncthreads();  // S1

            // GEMM1: all 256 threads; output (bl14, i14); weights in registers
            {
                unsigned long long acc0 = 0ull, acc1 = 0ull;
                #pragma unroll
                for (int qp = 0; qp < 16; ++qp) {
                    unsigned long long hx, hy;
                    lds_v2u64(yj_b + (unsigned)qp * 16u, hx, hy);
                    acc0 = fma2(hx, w1r[2 * qp], acc0);
                    acc1 = fma2(hy, w1r[2 * qp + 1], acc1);
                }
                float2 f0 = u2f(acc0), f1 = u2f(acc1);
                sm.h1[bl14][i14] = softplus_f((f0.x + f0.y) + (f1.x + f1.y) + sm.bf1v[i14]);
            }
            __syncthreads();  // S2

            // GEMM2: all 256 threads; output (bl14, i14); K=128 = 64 q, k-packed
            {
                unsigned long long acc0 = 0ull, acc1 = 0ull;
                #pragma unroll
                for (int q = 0; q < 64; q += 2) {
                    unsigned long long hx, hy;
                    lds_v2u64(h1_b + (unsigned)q * 8u, hx, hy);
                    acc0 = fma2(hx, lds64(w2_i + (unsigned)q * 1024u), acc0);
                    acc1 = fma2(hy, lds64(w2_i + (unsigned)(q + 1) * 1024u), acc1);
                }
                float2 f0 = u2f(acc0), f1 = u2f(acc1);
                float v = softplus_f((f0.x + f0.y) + (f1.x + f1.y) + sm.bf2v[i14]);
                sm.h2[row14][i14] = v;
                unsigned doff = (unsigned)(row14 * 128 + i14) * 4u;
                #pragma unroll
                for (int pe = 0; pe < 3; ++pe)
                    st_async32(peer_h2base[pe] + doff, v, peer_h2mbar[pe]);
            }
            __syncthreads();            // S3: local h2 rows visible
            mbar_wait(my_h2mbar, ph);   // peer h2 rows arrived

            // GEMM3: thread owns n_local = tid; 8 rows; K=128 = 64 q-pairs, ALL SMEM
            unsigned long long a0 = 0, a1 = 0, a2 = 0, a3 = 0;
            unsigned long long a4 = 0, a5 = 0, a6 = 0, a7 = 0;
            {
                unsigned wA = wcb;
                unsigned hA = h2b;
                #pragma unroll 8
                for (int qp = 0; qp < 64; qp += 2) {
                    unsigned long long w0 = lds64(wA);
                    unsigned long long w1 = lds64(wA + 2048u);
                    wA += 4096u;
                    unsigned long long h0x, h0y, h1x, h1y, h2x, h2y, h3x, h3y;
                    unsigned long long h4x, h4y, h5x, h5y, h6x, h6y, h7x, h7y;
                    lds_v2u64(hA,          h0x, h0y);
                    lds_v2u64(hA +  512u,  h1x, h1y);
                    lds_v2u64(hA + 1024u,  h2x, h2y);
                    lds_v2u64(hA + 1536u,  h3x, h3y);
                    lds_v2u64(hA + 2048u,  h4x, h4y);
                    lds_v2u64(hA + 2560u,  h5x, h5y);
                    lds_v2u64(hA + 3072u,  h6x, h6y);
                    lds_v2u64(hA + 3584u,  h7x, h7y);
                    hA += 16u;
                    a0 = fma2(h0x, w0, a0); a0 = fma2(h0y, w1, a0);
                    a1 = fma2(h1x, w0, a1); a1 = fma2(h1y, w1, a1);
                    a2 = fma2(h2x, w0, a2); a2 = fma2(h2y, w1, a2);
                    a3 = fma2(h3x, w0, a3); a3 = fma2(h3y, w1, a3);
                    a4 = fma2(h4x, w0, a4); a4 = fma2(h4y, w1, a4);
                    a5 = fma2(h5x, w0, a5); a5 = fma2(h5y, w1, a5);
                    a6 = fma2(h6x, w0, a6); a6 = fma2(h6y, w1, a6);
                    a7 = fma2(h7x, w0, a7); a7 = fma2(h7y, w1, a7);
                }
            }

            // epilogue: fold k-parity, tanh, einsum partial, 16-lane reduce (d)
            float z = sm.bf3loc[tid];
            float kv[8];
            {
                unsigned long long aa[8] = {a0, a1, a2, a3, a4, a5, a6, a7};
                #pragma unroll
                for (int b = 0; b < 8; ++b) {
                    float2 f = u2f(aa[b]);
                    float v = tanh_fast(f.x + f.y + z);
                    float p = v * sm.dx[b][d0];
                    p += __shfl_xor_sync(0xffffffffu, p, 1);
                    p += __shfl_xor_sync(0xffffffffu, p, 2);
                    p += __shfl_xor_sync(0xffffffffu, p, 4);
                    p += __shfl_xor_sync(0xffffffffu, p, 8);
                    kv[b] = p;
                }
            }
            if (writer) {
                #pragma unroll
                for (int b = 0; b < 8; ++b) sm.ks[j][s_g][b] = kv[b];
            }
            __syncthreads();  // S4: all GEMM3 reads of h2 done; local ks visible
            if (writer) {
                #pragma unroll
                for (int pb = 0; pb < 4; ++pb) {
                    unsigned long long v = pack2(kv[2 * pb], kv[2 * pb + 1]);
                    unsigned doff = (unsigned)(((j * 64 + s_g) * 8) + 2 * pb) * 4u;
                    #pragma unroll
                    for (int pe = 0; pe < 3; ++pe)
                        st_async64(peer_ksbase[pe] + doff, v, peer_ksmbar[pe]);
                }
            }
            mbar_wait(my_ksmbar, ph);  // peer ks arrived
            ph ^= 1;
        }

        // y += h * sum_j B_SOL[j] * ks[j]   (8 rows)
        for (int idx = tid; idx < 512; idx += NTHR) {
            int s = idx >> 3, b = idx & 7;
            float sum = 0.0f;
            #pragma unroll
            for (int j = 0; j < 6; ++j) sum += cBw[j] * sm.ks[j][s][b];
            sm.y[b][s] += h * sum;
        }
        __syncthreads();  // S5

        if (tid < 16) {  // out[:, t+1, :] for 2 local rows
            int bl = tid >> 3, o = tid & 7;
            int row = (int)rank * 2 + bl;
            float acc = br[o];
            #pragma unroll 8
            for (int s2 = 0; s2 < 64; ++s2) acc += sm.y[row][s2] * Wr[o * 64 + s2];
            out[((b0g + row) * 64 + (t + 1)) * 8 + o] = acc;
        }
    }
}

extern "C" void kernel_launch(void* const* d_in, const int* in_sizes, int n_in,
                              void* d_out, int out_size) {
    const float* ts      = (const float*)d_in[0];
    const float* coeff_d = (const float*)d_in[1];
    const float* coeff_c = (const float*)d_in[2];
    const float* coeff_b = (const float*)d_in[3];
    const float* coeff_a = (const float*)d_in[4];
    const float* Wi1 = (const float*)d_in[5];
    const float* bi1 = (const float*)d_in[6];
    const float* Wi2 = (const float*)d_in[7];
    const float* bi2 = (const float*)d_in[8];
    const float* Wf1 = (const float*)d_in[9];
    const float* bf1 = (const float*)d_in[10];
    const float* Wf2 = (const float*)d_in[11];
    const float* bf2 = (const float*)d_in[12];
    const float* Wf3 = (const float*)d_in[13];
    const float* bf3 = (const float*)d_in[14];
    const float* Wr  = (const float*)d_in[15];
    const float* br  = (const float*)d_in[16];
    float* out = (float*)d_out;

    cudaFuncSetAttribute(cde_kernel, cudaFuncAttributeMaxDynamicSharedMemorySize,
                         (int)sizeof(Smem));

    prep_kernel<<<512, PREPT>>>(Wf3);
    cde_kernel<<<128, NTHR, sizeof(Smem)>>>(ts, coeff_d, coeff_c, coeff_b, coeff_a,
                                            Wi1, bi1, Wi2, bi2, Wf1, bf1, Wf2, bf2,
                                            bf3, Wr, br, out);
}